// round 3
// baseline (speedup 1.0000x reference)
#include <cuda_runtime.h>
#include <math.h>

#define FIN 128
#define HC 256            // H*C layer1 output width
#define NH 8              // heads layer 1
#define C2 32             // channels layer 2
#define GG 64             // graphs
#define NCLS 10
#define MAXN 100000
#define MAXE 1600000

// ---------------- scratch (device globals; no allocation allowed) ------------
__device__ float g_h1[MAXN * HC];          // x @ W1           (102.4 MB)
__device__ float g_out1[MAXN * HC];        // elu(gat1 + b1)   (102.4 MB)
__device__ float g_as1[MAXN * NH];
__device__ float g_ad1[MAXN * NH];
__device__ float g_h2[MAXN * C2];
__device__ float g_as2[MAXN];
__device__ float g_ad2[MAXN];
__device__ float g_p[MAXE * NH];           // per-edge softmax numerators (51.2 MB)
__device__ int   g_deg[MAXN];
__device__ int   g_rowptr[MAXN + 1];
__device__ int   g_cursor[MAXN];
__device__ int   g_csrc[MAXE];
__device__ int   g_bsum[128];
__device__ float g_pool[GG * C2];
__device__ float g_cnt[GG];

__device__ __forceinline__ float lrelu(float v) { return fmaxf(v, 0.2f * v); }

// ---------------- init ------------------------------------------------------
__global__ void k_init(int n) {
    int g = blockIdx.x * blockDim.x + threadIdx.x;
    if (g < n) g_deg[g] = 0;
    if (g < GG * C2) g_pool[g] = 0.f;
    if (g < GG) g_cnt[g] = 0.f;
}

// ---------------- CSR build: histogram -> scan -> scatter -------------------
__global__ void k_hist(const int* __restrict__ ei, int E) {
    int e = blockIdx.x * blockDim.x + threadIdx.x;
    if (e < E) atomicAdd(&g_deg[ei[E + e]], 1);
}

__global__ void k_scan1(int n) {
    __shared__ int s[1024];
    int t = threadIdx.x;
    int g = blockIdx.x * 1024 + t;
    int v = (g < n) ? g_deg[g] : 0;
    s[t] = v;
    __syncthreads();
    for (int off = 1; off < 1024; off <<= 1) {
        int u = 0;
        if (t >= off) u = s[t - off];
        __syncthreads();
        if (t >= off) s[t] += u;
        __syncthreads();
    }
    if (g < n) g_rowptr[g] = s[t] - v;          // exclusive, chunk-local
    if (t == 1023) g_bsum[blockIdx.x] = s[1023];
}

__global__ void k_scan2(int nb) {
    int run = 0;
    for (int i = 0; i < nb; i++) { int v = g_bsum[i]; g_bsum[i] = run; run += v; }
}

__global__ void k_scan3(int n, int E) {
    int g = blockIdx.x * 1024 + threadIdx.x;
    if (g < n) {
        int v = g_rowptr[g] + g_bsum[blockIdx.x];
        g_rowptr[g] = v;
        g_cursor[g] = v;
    }
    if (g == 0) g_rowptr[n] = E;
}

__global__ void k_scatter(const int* __restrict__ ei, int E) {
    int e = blockIdx.x * blockDim.x + threadIdx.x;
    if (e < E) {
        int s = ei[e];
        int d = ei[E + e];
        int pos = atomicAdd(&g_cursor[d], 1);
        g_csrc[pos] = s;
    }
}

// ---------------- GEMM1: h1 = x @ W1, plus attention scores -----------------
// block = 256 threads, 8 nodes per block, thread t owns output column t.
__global__ void k_gemm1(const float* __restrict__ x, const float* __restrict__ W1,
                        const float* __restrict__ asw, const float* __restrict__ adw, int n) {
    __shared__ float4 xs4[8][FIN / 4];
    float* xs = (float*)xs4;
    int t = threadIdx.x;
    int n0 = blockIdx.x * 8;
    for (int idx = t; idx < 8 * FIN; idx += 256) {
        int j = idx >> 7, k = idx & 127;
        int nn = n0 + j;
        xs[j * FIN + k] = (nn < n) ? x[nn * FIN + k] : 0.f;
    }
    __syncthreads();
    float acc[8] = {0.f, 0.f, 0.f, 0.f, 0.f, 0.f, 0.f, 0.f};
#pragma unroll 4
    for (int k4 = 0; k4 < FIN / 4; k4++) {
        int k = k4 * 4;
        float w0 = W1[(k + 0) * HC + t];
        float w1 = W1[(k + 1) * HC + t];
        float w2 = W1[(k + 2) * HC + t];
        float w3 = W1[(k + 3) * HC + t];
#pragma unroll
        for (int j = 0; j < 8; j++) {
            float4 a = xs4[j][k4];
            acc[j] += a.x * w0 + a.y * w1 + a.z * w2 + a.w * w3;
        }
    }
    int lane = t & 31;
    int h = t >> 5;          // warp == head
    float aw = asw[t], dw = adw[t];
#pragma unroll
    for (int j = 0; j < 8; j++) {
        int nn = n0 + j;
        if (nn < n) g_h1[nn * HC + t] = acc[j];
        float vs = acc[j] * aw, vd = acc[j] * dw;
#pragma unroll
        for (int off = 16; off; off >>= 1) {
            vs += __shfl_xor_sync(0xffffffffu, vs, off);
            vd += __shfl_xor_sync(0xffffffffu, vd, off);
        }
        if (lane == 0 && nn < n) { g_as1[nn * NH + h] = vs; g_ad1[nn * NH + h] = vd; }
    }
}

// ---------------- GAT layer 1: one warp per destination node ----------------
__global__ void k_gat1(const float* __restrict__ b1, int n) {
    int w = (blockIdx.x * blockDim.x + threadIdx.x) >> 5;
    int lane = threadIdx.x & 31;
    if (w >= n) return;
    int base = g_rowptr[w];
    int d = g_rowptr[w + 1] - base;

    float ad[NH], mx[NH], eself[NH];
#pragma unroll
    for (int h = 0; h < NH; h++) {
        ad[h] = g_ad1[w * NH + h];
        float e = lrelu(g_as1[w * NH + h] + ad[h]);   // self-loop score
        eself[h] = e;
        mx[h] = e;
    }
    // pass 1: per-head max (lanes parallel over edges)
    for (int i = lane; i < d; i += 32) {
        int s = g_csrc[base + i];
#pragma unroll
        for (int h = 0; h < NH; h++) {
            float e = lrelu(g_as1[s * NH + h] + ad[h]);
            mx[h] = fmaxf(mx[h], e);
        }
    }
#pragma unroll
    for (int h = 0; h < NH; h++)
#pragma unroll
        for (int off = 16; off; off >>= 1)
            mx[h] = fmaxf(mx[h], __shfl_xor_sync(0xffffffffu, mx[h], off));

    // pass 2: p = exp(e - m), stage to g_p, accumulate z
    float z[NH] = {0.f, 0.f, 0.f, 0.f, 0.f, 0.f, 0.f, 0.f};
    for (int i = lane; i < d; i += 32) {
        int s = g_csrc[base + i];
#pragma unroll
        for (int h = 0; h < NH; h++) {
            float e = lrelu(g_as1[s * NH + h] + ad[h]);
            float p = __expf(e - mx[h]);
            z[h] += p;
            g_p[(base + i) * NH + h] = p;
        }
    }
#pragma unroll
    for (int h = 0; h < NH; h++)
#pragma unroll
        for (int off = 16; off; off >>= 1)
            z[h] += __shfl_xor_sync(0xffffffffu, z[h], off);

    // pass 3: gather-accumulate (whole warp cooperates per edge, lane = channel)
    float acc[NH];
#pragma unroll
    for (int h = 0; h < NH; h++) {
        float ps = __expf(eself[h] - mx[h]);
        z[h] += ps;
        acc[h] = ps * g_h1[w * HC + h * 32 + lane];
    }
    for (int i = 0; i < d; i++) {
        int s = g_csrc[base + i];
        float pv = (lane < NH) ? g_p[(base + i) * NH + lane] : 0.f;
        const float* hp = &g_h1[s * HC + lane];
#pragma unroll
        for (int h = 0; h < NH; h++)
            acc[h] += __shfl_sync(0xffffffffu, pv, h) * hp[h * 32];
    }
#pragma unroll
    for (int h = 0; h < NH; h++) {
        float o = acc[h] / (z[h] + 1e-16f) + b1[h * 32 + lane];
        o = (o > 0.f) ? o : expm1f(o);                // ELU
        g_out1[w * HC + h * 32 + lane] = o;
    }
}

// ---------------- GEMM2: h2 = out1 @ W2 (+ scores). warp = 4 nodes ----------
__global__ void k_gemm2(const float* __restrict__ W2, const float* __restrict__ asw2,
                        const float* __restrict__ adw2, int n) {
    __shared__ float4 rs4[32][HC / 4];
    float* rs = (float*)rs4;
    int t = threadIdx.x;
    int n0 = blockIdx.x * 32;
    for (int idx = t; idx < 32 * HC; idx += 256) {
        int j = idx >> 8, k = idx & 255;
        int nn = n0 + j;
        rs[j * HC + k] = (nn < n) ? g_out1[nn * HC + k] : 0.f;
    }
    __syncthreads();
    int lane = t & 31, wi = t >> 5;
    float acc[4] = {0.f, 0.f, 0.f, 0.f};
#pragma unroll 4
    for (int k4 = 0; k4 < HC / 4; k4++) {
        int k = k4 * 4;
        float w0 = W2[(k + 0) * C2 + lane];
        float w1 = W2[(k + 1) * C2 + lane];
        float w2v = W2[(k + 2) * C2 + lane];
        float w3 = W2[(k + 3) * C2 + lane];
#pragma unroll
        for (int j = 0; j < 4; j++) {
            float4 a = rs4[wi * 4 + j][k4];
            acc[j] += a.x * w0 + a.y * w1 + a.z * w2v + a.w * w3;
        }
    }
    float aw = asw2[lane], dw = adw2[lane];
#pragma unroll
    for (int j = 0; j < 4; j++) {
        int nn = n0 + wi * 4 + j;
        float vs = acc[j] * aw, vd = acc[j] * dw;
#pragma unroll
        for (int off = 16; off; off >>= 1) {
            vs += __shfl_xor_sync(0xffffffffu, vs, off);
            vd += __shfl_xor_sync(0xffffffffu, vd, off);
        }
        if (nn < n) {
            g_h2[nn * C2 + lane] = acc[j];
            if (lane == 0) { g_as2[nn] = vs; g_ad2[nn] = vd; }
        }
    }
}

// ---------------- GAT layer 2 (1 head) + pooling atomics --------------------
__global__ void k_gat2(const float* __restrict__ b2, const int* __restrict__ batch, int n) {
    int w = (blockIdx.x * blockDim.x + threadIdx.x) >> 5;
    int lane = threadIdx.x & 31;
    if (w >= n) return;
    int base = g_rowptr[w];
    int d = g_rowptr[w + 1] - base;
    float adn = g_ad2[w];
    float e0 = lrelu(g_as2[w] + adn);
    float mx = e0;
    for (int i = lane; i < d; i += 32)
        mx = fmaxf(mx, lrelu(g_as2[g_csrc[base + i]] + adn));
#pragma unroll
    for (int off = 16; off; off >>= 1)
        mx = fmaxf(mx, __shfl_xor_sync(0xffffffffu, mx, off));
    float z = 0.f;
    for (int i = lane; i < d; i += 32) {
        float e = lrelu(g_as2[g_csrc[base + i]] + adn);
        float p = __expf(e - mx);
        z += p;
        g_p[base + i] = p;
    }
#pragma unroll
    for (int off = 16; off; off >>= 1)
        z += __shfl_xor_sync(0xffffffffu, z, off);
    float ps = __expf(e0 - mx);
    z += ps;
    float acc = ps * g_h2[w * C2 + lane];
    for (int i = 0; i < d; i++) {
        int s = g_csrc[base + i];
        acc += g_p[base + i] * g_h2[s * C2 + lane];
    }
    float val = acc / (z + 1e-16f) + b2[lane];
    int g = batch[w];
    atomicAdd(&g_pool[g * C2 + lane], val);
    if (lane == 0) atomicAdd(&g_cnt[g], 1.f);
}

// ---------------- final: mean-pool normalize + linear head ------------------
__global__ void k_final(const float* __restrict__ Wlin, const float* __restrict__ blin,
                        float* __restrict__ out) {
    int t = threadIdx.x;
    if (t >= GG * NCLS) return;
    int g = t / NCLS, c = t - g * NCLS;
    float inv = 1.f / fmaxf(g_cnt[g], 1.f);
    float acc = blin[c];
#pragma unroll
    for (int k = 0; k < C2; k++)
        acc += g_pool[g * C2 + k] * inv * Wlin[k * NCLS + c];
    out[t] = acc;
}

// ---------------- launch ----------------------------------------------------
extern "C" void kernel_launch(void* const* d_in, const int* in_sizes, int n_in,
                              void* d_out, int out_size) {
    const float* x    = (const float*)d_in[0];
    const int*   ei   = (const int*)d_in[1];
    const int*   batch= (const int*)d_in[2];
    const float* W1   = (const float*)d_in[3];
    const float* asw1 = (const float*)d_in[4];
    const float* adw1 = (const float*)d_in[5];
    const float* b1   = (const float*)d_in[6];
    const float* W2   = (const float*)d_in[7];
    const float* asw2 = (const float*)d_in[8];
    const float* adw2 = (const float*)d_in[9];
    const float* b2   = (const float*)d_in[10];
    const float* Wlin = (const float*)d_in[11];
    const float* blin = (const float*)d_in[12];
    float* out = (float*)d_out;

    int n = in_sizes[0] / FIN;
    int E = in_sizes[1] / 2;
    int nb = (n + 1023) / 1024;

    k_init<<<(n + 255) / 256, 256>>>(n);
    k_hist<<<(E + 255) / 256, 256>>>(ei, E);
    k_scan1<<<nb, 1024>>>(n);
    k_scan2<<<1, 1>>>(nb);
    k_scan3<<<nb, 1024>>>(n, E);
    k_scatter<<<(E + 255) / 256, 256>>>(ei, E);
    k_gemm1<<<(n + 7) / 8, 256>>>(x, W1, asw1, adw1, n);
    k_gat1<<<(n + 7) / 8, 256>>>(b1, n);
    k_gemm2<<<(n + 31) / 32, 256>>>(W2, asw2, adw2, n);
    k_gat2<<<(n + 7) / 8, 256>>>(b2, batch, n);
    k_final<<<1, GG * NCLS>>>(Wlin, blin, out);
}